// round 2
// baseline (speedup 1.0000x reference)
#include <cuda_runtime.h>
#include <float.h>

#define B_   32
#define D_   512
#define HW_  1024
#define N_   32768          // B_*HW_
#define K_   4096

#define BM 64
#define BN 128
#define BD 16

// ---- scratch (no allocations allowed) ----
__device__ float  g_Et[D_ * K_];   // transposed embeddings [d][k], 8 MB
__device__ float  g_esq[K_];       // ||e_k||^2
__device__ int    g_kidx[N_];      // argmin per token
__device__ double g_loss;          // sum of (z-q)^2

// ============================================================
// K0a: transpose E[K_][D_] -> Et[D_][K_]
// ============================================================
__global__ void k_transpose(const float* __restrict__ E) {
    __shared__ float tile[32][33];
    int k0 = blockIdx.x * 32, d0 = blockIdx.y * 32;
    int tx = threadIdx.x, ty = threadIdx.y;   // blockDim (32, 8)
#pragma unroll
    for (int i = 0; i < 32; i += 8)
        tile[ty + i][tx] = E[(size_t)(k0 + ty + i) * D_ + d0 + tx];
    __syncthreads();
#pragma unroll
    for (int i = 0; i < 32; i += 8)
        g_Et[(size_t)(d0 + ty + i) * K_ + k0 + tx] = tile[tx][ty + i];
}

// ============================================================
// K0b: ||e_k||^2 per code row; also zero the loss accumulator
// ============================================================
__global__ void k_esq(const float* __restrict__ E) {
    int row = blockIdx.x;
    int t = threadIdx.x;                      // 128 threads
    float s = 0.f;
#pragma unroll
    for (int i = t; i < D_; i += 128) {
        float v = E[(size_t)row * D_ + i];
        s += v * v;
    }
#pragma unroll
    for (int o = 16; o > 0; o >>= 1) s += __shfl_down_sync(0xffffffffu, s, o);
    __shared__ float sb[4];
    if ((t & 31) == 0) sb[t >> 5] = s;
    __syncthreads();
    if (t == 0) {
        g_esq[row] = sb[0] + sb[1] + sb[2] + sb[3];
        if (row == 0) g_loss = 0.0;
    }
}

// ============================================================
// K1: fused distance GEMM + argmin.
//   dist(n,k) = ||e_k||^2 - 2 * dot(z_n, e_k)   (||z||^2 dropped: row-constant)
// Block: 64 tokens (BM). Iterates code tiles of BN=128, D in chunks of BD=16.
// Inner loop uses packed fma.rn.f32x2 (FFMA2): rows paired in f32x2 lanes,
// B values stored duplicated in smem so one LDS.64 yields (b,b).
// ============================================================
__global__ void __launch_bounds__(128) k_argmin(const float* __restrict__ X) {
    __shared__ float  As[BD][BM];         // 4 KB
    __shared__ float  Bs2[BD][2 * BN];    // 16 KB (duplicated pairs)
    __shared__ float  esqs[BN];
    __shared__ float2 red[BM][16];        // 8 KB

    int t  = threadIdx.x;
    int tx = t & 15;          // 16 column groups
    int ty = t >> 4;          // 8 row groups (8 rows each)
    int base = blockIdx.x * BM;
    int b   = base >> 10;
    int hw0 = base & 1023;
    const float* Xb = X + (size_t)b * D_ * HW_ + hw0;

    float bmv[8];
    int   bmi[8];
#pragma unroll
    for (int r = 0; r < 8; r++) { bmv[r] = FLT_MAX; bmi[r] = 0; }

    for (int ct = 0; ct < K_ / BN; ct++) {
        int n0 = ct * BN;
        __syncthreads();                  // protect esqs from previous readers
        esqs[t] = g_esq[n0 + t];          // 128 threads, BN=128

        unsigned long long acc[4][8];
#pragma unroll
        for (int p = 0; p < 4; p++)
#pragma unroll
            for (int j = 0; j < 8; j++) acc[p][j] = 0ull;

        for (int dc = 0; dc < D_ / BD; dc++) {
            int d0 = dc * BD;
            // A tile: 16 x 64, coalesced (tokens contiguous in hw)
#pragma unroll
            for (int i = 0; i < 8; i++) {
                int dd = i * 2 + (t >> 6);
                int m  = t & 63;
                As[dd][m] = Xb[(size_t)(d0 + dd) * HW_ + m];
            }
            // B tile duplicated: Bs2[dd][2c], Bs2[dd][2c+1] = Et[d0+dd][n0+c]
#pragma unroll
            for (int i = 0; i < BD; i++) {
                float v = g_Et[(size_t)(d0 + i) * K_ + n0 + t];
                Bs2[i][2 * t]     = v;
                Bs2[i][2 * t + 1] = v;
            }
            __syncthreads();
#pragma unroll
            for (int dd = 0; dd < BD; dd++) {
                // 8 rows = 4 f32x2 pairs, loaded as two 16B vectors
                ulonglong2 a0 = *(const ulonglong2*)&As[dd][ty * 8];
                ulonglong2 a1 = *(const ulonglong2*)&As[dd][ty * 8 + 4];
                unsigned long long ap[4] = {a0.x, a0.y, a1.x, a1.y};
#pragma unroll
                for (int j = 0; j < 8; j++) {
                    unsigned long long bj =
                        *(const unsigned long long*)&Bs2[dd][2 * (tx + 16 * j)];
#pragma unroll
                    for (int p = 0; p < 4; p++) {
                        asm("fma.rn.f32x2 %0, %1, %2, %0;"
                            : "+l"(acc[p][j]) : "l"(ap[p]), "l"(bj));
                    }
                }
            }
            __syncthreads();              // protect smem before next-chunk stores
        }
        // epilogue for this code tile: update running min (first-index ties)
#pragma unroll
        for (int j = 0; j < 8; j++) {
            int   c = tx + 16 * j;
            float e = esqs[c];
            int   idx = n0 + c;
#pragma unroll
            for (int p = 0; p < 4; p++) {
                float dlo = e - 2.f * __uint_as_float((unsigned)(acc[p][j] & 0xffffffffull));
                float dhi = e - 2.f * __uint_as_float((unsigned)(acc[p][j] >> 32));
                int r0 = 2 * p, r1 = 2 * p + 1;
                if (dlo < bmv[r0]) { bmv[r0] = dlo; bmi[r0] = idx; }
                if (dhi < bmv[r1]) { bmv[r1] = dhi; bmi[r1] = idx; }
            }
        }
    }
    // cross-thread reduction: row r has 16 candidates (one per tx)
    __syncthreads();
#pragma unroll
    for (int r = 0; r < 8; r++)
        red[ty * 8 + r][tx] = make_float2(bmv[r], __int_as_float(bmi[r]));
    __syncthreads();
    if (t < BM) {
        float2 best = red[t][0];
#pragma unroll
        for (int x = 1; x < 16; x++) {
            float2 c = red[t][x];
            if (c.x < best.x ||
                (c.x == best.x && __float_as_int(c.y) < __float_as_int(best.y)))
                best = c;
        }
        g_kidx[base + t] = __float_as_int(best.y);
    }
}

// ============================================================
// K2: gather q = E[k], write NCHW output through a 64x64 smem
// transpose tile (coalesced stores), fuse loss partial sum.
// ============================================================
__global__ void __launch_bounds__(256) k_output(const float* __restrict__ X,
                                                const float* __restrict__ E,
                                                float* __restrict__ out) {
    __shared__ float S[64][65];
    __shared__ int   karr[64];
    __shared__ float rbuf[8];
    int t = threadIdx.x;
    int base = blockIdx.x * 64;
    int b   = base >> 10;
    int hw0 = base & 1023;
    if (t < 64) karr[t] = g_kidx[base + t];
    __syncthreads();

    float lsum = 0.f;
    size_t blk_base = (size_t)b * D_ * HW_ + hw0;
    for (int dc = 0; dc < D_; dc += 64) {
        // load Q tile: token m, dims dc..dc+63, coalesced along d
#pragma unroll
        for (int i = 0; i < 4; i++) {
            int m  = (t >> 4) + i * 16;
            int dl = (t & 15) * 4;
            float4 q = *(const float4*)&E[(size_t)karr[m] * D_ + dc + dl];
            S[m][dl] = q.x; S[m][dl + 1] = q.y; S[m][dl + 2] = q.z; S[m][dl + 3] = q.w;
        }
        __syncthreads();
        // write phase: coalesced over hw for each d; fuse (z-q)^2
        int hwl = t & 63;
#pragma unroll
        for (int i = 0; i < 16; i++) {
            int dl = (t >> 6) + i * 4;
            size_t addr = blk_base + (size_t)(dc + dl) * HW_ + hwl;
            float z = X[addr];
            float q = S[hwl][dl];
            float df = z - q;
            lsum += df * df;
            out[addr] = q;
        }
        __syncthreads();
    }
#pragma unroll
    for (int o = 16; o > 0; o >>= 1) lsum += __shfl_down_sync(0xffffffffu, lsum, o);
    if ((t & 31) == 0) rbuf[t >> 5] = lsum;
    __syncthreads();
    if (t == 0) {
        float s = 0.f;
#pragma unroll
        for (int w = 0; w < 8; w++) s += rbuf[w];
        atomicAdd(&g_loss, (double)s);
    }
}

// ============================================================
// K3: loss = 1.25 * mean((z-q)^2)
// ============================================================
__global__ void k_finalize(float* __restrict__ out, int out_size) {
    if (out_size > N_ * D_)
        out[N_ * D_] = (float)(1.25 * g_loss / ((double)N_ * (double)D_));
}

// ============================================================
extern "C" void kernel_launch(void* const* d_in, const int* in_sizes, int n_in,
                              void* d_out, int out_size) {
    const float* X = (const float*)d_in[0];   // [32,512,32,32]
    const float* E = (const float*)d_in[1];   // [4096,512]
    if (n_in >= 2 && in_sizes[0] == K_ * D_ && in_sizes[1] == N_ * D_) {
        // defensive: swapped metadata order
        const float* tmp = X; X = E; E = tmp;
    }
    float* out = (float*)d_out;

    k_transpose<<<dim3(K_ / 32, D_ / 32), dim3(32, 8)>>>(E);
    k_esq<<<K_, 128>>>(E);
    k_argmin<<<N_ / BM, 128>>>(X);
    k_output<<<N_ / 64, 256>>>(X, E, out);
    k_finalize<<<1, 1>>>(out, out_size);
}

// round 6
// speedup vs baseline: 3.5589x; 3.5589x over previous
#include <cuda_runtime.h>
#include <cuda_bf16.h>
#include <float.h>
#include <stdint.h>

#define B_   32
#define D_   512
#define HW_  1024
#define N_   32768
#define K_   4096

#define TOK_PER_CTA 128
#define NTILE       128                  // codes per tile
#define NUM_TILES   (K_ / NTILE)         // 32
#define NCH         4                    // k-chunks per tile (128 halves each)
#define GCHUNKS     (NUM_TILES * NCH)    // 128
#define CAP         64
#define MARGIN_F    1.5f

// ---- smem layout (bytes) ----
#define AP_B      1040                   // A row pitch: (512+8)*2
#define BP_B      272                    // B row pitch: (128+8)*2
#define BBUF_B    (128 * BP_B)           // 34816 per buffer
#define SM_A      0                      // 128 * 1040 = 133120
#define SM_B      133120                 // 2 * 34816 = 69632
#define SM_ESQ    202752                 // 128 floats
#define SM_SCNT   203264                 // 128 ints
#define SM_WMIN   203776                 // 128 * 2 * float2 = 2048
#define SM_TOTAL  205824

// ---- scratch ----
__device__ __nv_bfloat16 g_Zh[(size_t)N_ * D_];
__device__ float         g_Zf[(size_t)N_ * D_];
__device__ __nv_bfloat16 g_Eh[(size_t)K_ * D_];
__device__ float         g_esq[K_];
__device__ float2        g_cand[N_][CAP];
__device__ int           g_ccnt[N_];
__device__ float         g_amin[N_];
__device__ int           g_kidx[N_];
__device__ double        g_loss;

// ================= helpers =================
__device__ __forceinline__ uint32_t smem_u32(const void* p) {
    uint32_t a;
    asm("{ .reg .u64 t; cvta.to.shared.u64 t, %1; cvt.u32.u64 %0, t; }" : "=r"(a) : "l"(p));
    return a;
}
__device__ __forceinline__ void ldsm_x4(uint32_t& r0, uint32_t& r1, uint32_t& r2, uint32_t& r3,
                                        uint32_t addr) {
    asm volatile("ldmatrix.sync.aligned.m8n8.x4.shared.b16 {%0,%1,%2,%3}, [%4];"
                 : "=r"(r0), "=r"(r1), "=r"(r2), "=r"(r3) : "r"(addr));
}
__device__ __forceinline__ void mma16816(float* d, const uint32_t* a, const uint32_t* b) {
    asm volatile("mma.sync.aligned.m16n8k16.row.col.f32.bf16.bf16.f32 "
                 "{%0,%1,%2,%3}, {%4,%5,%6,%7}, {%8,%9}, {%0,%1,%2,%3};"
                 : "+f"(d[0]), "+f"(d[1]), "+f"(d[2]), "+f"(d[3])
                 : "r"(a[0]), "r"(a[1]), "r"(a[2]), "r"(a[3]), "r"(b[0]), "r"(b[1]));
}
__device__ __forceinline__ void cp16(uint32_t dst, const void* src) {
    asm volatile("cp.async.ca.shared.global [%0], [%1], 16;" :: "r"(dst), "l"(src));
}
#define CP_COMMIT() asm volatile("cp.async.commit_group;" ::: "memory")
#define CP_WAIT0()  asm volatile("cp.async.wait_group 0;" ::: "memory")

// ============================================================
// K0: X[NCHW] -> Zf fp32 + Zh bf16 (token-major)
// ============================================================
__global__ void k_prep_z(const float* __restrict__ X) {
    __shared__ float tile[32][33];
    int b = blockIdx.z, d0 = blockIdx.y * 32, hw0 = blockIdx.x * 32;
    int tx = threadIdx.x, ty = threadIdx.y;       // (32, 8)
#pragma unroll
    for (int i = 0; i < 32; i += 8)
        tile[ty + i][tx] = X[((size_t)b * D_ + d0 + ty + i) * HW_ + hw0 + tx];
    __syncthreads();
#pragma unroll
    for (int i = 0; i < 32; i += 8) {
        size_t idx = (size_t)(b * HW_ + hw0 + ty + i) * D_ + d0 + tx;
        float v = tile[tx][ty + i];
        g_Zf[idx] = v;
        g_Zh[idx] = __float2bfloat16(v);
    }
}

// ============================================================
// K1: E -> Eh bf16 + ||e||^2; zero loss
// ============================================================
__global__ void k_prep_e(const float* __restrict__ E) {
    int row = blockIdx.x, t = threadIdx.x;        // 128 threads
    float s = 0.f;
#pragma unroll
    for (int i = t; i < D_; i += 128) {
        float v = E[(size_t)row * D_ + i];
        g_Eh[(size_t)row * D_ + i] = __float2bfloat16(v);
        s += v * v;
    }
#pragma unroll
    for (int o = 16; o > 0; o >>= 1) s += __shfl_down_sync(0xffffffffu, s, o);
    __shared__ float sb[4];
    if ((t & 31) == 0) sb[t >> 5] = s;
    __syncthreads();
    if (t == 0) {
        g_esq[row] = sb[0] + sb[1] + sb[2] + sb[3];
        if (row == 0) g_loss = 0.0;
    }
}

// ============================================================
// K2: bf16 mma.sync GEMM + margin argmin / candidate collection
// ============================================================
__global__ void __launch_bounds__(256, 1) k_gemm() {
    extern __shared__ char smem[];
    uint32_t sbase = smem_u32(smem);
    int tid = threadIdx.x;
    int lane = tid & 31, wid = tid >> 5;
    int wm = wid >> 1, wn = wid & 1;
    int tok0 = blockIdx.x * TOK_PER_CTA;

    float* esq_s = (float*)(smem + SM_ESQ);
    int*   scnt  = (int*)(smem + SM_SCNT);
    float2* wmin = (float2*)(smem + SM_WMIN);

    if (tid < 128) scnt[tid] = 0;

    // ---- load A resident: 128 tokens x 512 bf16, padded rows ----
    {
        const uint4* src = (const uint4*)(g_Zh + (size_t)tok0 * D_);
        for (int i = tid; i < 128 * 64; i += 256) {
            int r = i >> 6, c = i & 63;
            uint4 v = src[(size_t)r * 64 + c];
            *(uint4*)(smem + SM_A + r * AP_B + c * 16) = v;
        }
    }

    // per-lane ldmatrix base addresses
    uint32_t aAddr[2];
#pragma unroll
    for (int mf = 0; mf < 2; mf++) {
        int rowA = wm * 32 + mf * 16 + (lane & 15);
        aAddr[mf] = sbase + SM_A + rowA * AP_B + ((lane >> 4) * 8) * 2;
    }
    uint32_t bAddr[4];
#pragma unroll
    for (int n16 = 0; n16 < 4; n16++) {
        int rowB = wn * 64 + n16 * 16 + (lane & 7) + ((lane >> 4) << 3);
        bAddr[n16] = sbase + SM_B + rowB * BP_B + (((lane >> 3) & 1) * 8) * 2;
    }

    // prefetch chunk 0 of tile 0
    {
        int row = tid >> 1, half = tid & 1;
        const __nv_bfloat16* src = g_Eh + (size_t)row * D_ + half * 64;
        uint32_t dst = sbase + SM_B + row * BP_B + half * 128;
#pragma unroll
        for (int i = 0; i < 8; i++) cp16(dst + i * 16, src + i * 8);
        CP_COMMIT();
    }

    float acc[2][8][4];
#pragma unroll
    for (int mf = 0; mf < 2; mf++)
#pragma unroll
        for (int nf = 0; nf < 8; nf++)
#pragma unroll
            for (int v = 0; v < 4; v++) acc[mf][nf][v] = 0.f;

    float runmin[4]; int runk[4];
#pragma unroll
    for (int s = 0; s < 4; s++) { runmin[s] = FLT_MAX; runk[s] = 0; }

    for (int g = 0; g < GCHUNKS; g++) {
        CP_WAIT0();
        __syncthreads();

        if ((g & 3) == 0 && tid < 128)
            esq_s[tid] = g_esq[(g >> 2) * NTILE + tid];

        // prefetch next chunk into the other buffer
        if (g + 1 < GCHUNKS) {
            int gn = g + 1;
            int n0n = (gn >> 2) * NTILE;
            int row = tid >> 1, half = tid & 1;
            const __nv_bfloat16* src =
                g_Eh + (size_t)(n0n + row) * D_ + (gn & 3) * 128 + half * 64;
            uint32_t dst = sbase + SM_B + (gn & 1) * BBUF_B + row * BP_B + half * 128;
#pragma unroll
            for (int i = 0; i < 8; i++) cp16(dst + i * 16, src + i * 8);
            CP_COMMIT();
        }

        // ---- compute 8 k-steps on buffer g&1 ----
        uint32_t kbA = (uint32_t)((g & 3) * 256);      // byte offset in A cols
        uint32_t bb  = (uint32_t)((g & 1) * BBUF_B);
#pragma unroll
        for (int ks = 0; ks < 8; ks++) {
            uint32_t a0[4], a1[4];
            ldsm_x4(a0[0], a0[1], a0[2], a0[3], aAddr[0] + kbA + ks * 32);
            ldsm_x4(a1[0], a1[1], a1[2], a1[3], aAddr[1] + kbA + ks * 32);
            uint32_t bfr[8][2];
#pragma unroll
            for (int n16 = 0; n16 < 4; n16++)
                ldsm_x4(bfr[2 * n16][0], bfr[2 * n16][1],
                        bfr[2 * n16 + 1][0], bfr[2 * n16 + 1][1],
                        bAddr[n16] + bb + ks * 32);
#pragma unroll
            for (int nf = 0; nf < 8; nf++) {
                mma16816(acc[0][nf], a0, bfr[nf]);
                mma16816(acc[1][nf], a1, bfr[nf]);
            }
        }

        // ---- tile epilogue after last chunk ----
        if ((g & 3) == 3) {
            int n0 = (g >> 2) * NTILE;
            // stage the 16 esq values this lane needs
            float es[16];
#pragma unroll
            for (int nf = 0; nf < 8; nf++) {
#pragma unroll
                for (int p = 0; p < 2; p++)
                    es[nf * 2 + p] = esq_s[wn * 64 + nf * 8 + (lane & 3) * 2 + p];
            }
            // pass 1: per-lane slot minima  (slot = mf*2 + rowhalf)
            float sm[4]; int sk[4];
#pragma unroll
            for (int s = 0; s < 4; s++) { sm[s] = FLT_MAX; sk[s] = 0; }
#pragma unroll
            for (int mf = 0; mf < 2; mf++)
#pragma unroll
                for (int nf = 0; nf < 8; nf++)
#pragma unroll
                    for (int v = 0; v < 4; v++) {
                        float dist = fmaf(-2.f, acc[mf][nf][v], es[nf * 2 + (v & 1)]);
                        int slot = mf * 2 + (v >> 1);
                        int k = n0 + wn * 64 + nf * 8 + (lane & 3) * 2 + (v & 1);
                        if (dist < sm[slot]) { sm[slot] = dist; sk[slot] = k; }
                    }
            // quad reduce (lanes sharing a row)
#pragma unroll
            for (int off = 1; off <= 2; off <<= 1) {
#pragma unroll
                for (int s = 0; s < 4; s++) {
                    float od = __shfl_xor_sync(0xffffffffu, sm[s], off);
                    int   ok = __shfl_xor_sync(0xffffffffu, sk[s], off);
                    if (od < sm[s] || (od == sm[s] && ok < sk[s])) { sm[s] = od; sk[s] = ok; }
                }
            }
#pragma unroll
            for (int s = 0; s < 4; s++)
                if (sm[s] < runmin[s]) { runmin[s] = sm[s]; runk[s] = sk[s]; }
            // pass 2: margin appends
#pragma unroll
            for (int mf = 0; mf < 2; mf++)
#pragma unroll
                for (int nf = 0; nf < 8; nf++)
#pragma unroll
                    for (int v = 0; v < 4; v++) {
                        float dist = fmaf(-2.f, acc[mf][nf][v], es[nf * 2 + (v & 1)]);
                        int slot = mf * 2 + (v >> 1);
                        if (dist < runmin[slot] + MARGIN_F) {
                            int row = wm * 32 + mf * 16 + (lane >> 2) + (v >> 1) * 8;
                            int k = n0 + wn * 64 + nf * 8 + (lane & 3) * 2 + (v & 1);
                            int s = atomicAdd(&scnt[row], 1);
                            if (s < CAP)
                                g_cand[tok0 + row][s] =
                                    make_float2(dist, __int_as_float(k));
                        }
                        acc[mf][nf][v] = 0.f;   // reset for next tile
                    }
        }
        __syncthreads();
    }

    // ---- final: per-warp row minima -> smem -> global ----
    if ((lane & 3) == 0) {
#pragma unroll
        for (int s = 0; s < 4; s++) {
            int mf = s >> 1, rh = s & 1;
            int row = wm * 32 + mf * 16 + (lane >> 2) + rh * 8;
            wmin[row * 2 + wn] = make_float2(runmin[s], __int_as_float(runk[s]));
        }
    }
    __syncthreads();
    if (tid < 128) {
        float2 a = wmin[tid * 2 + 0], b = wmin[tid * 2 + 1];
        g_amin[tok0 + tid] = fminf(a.x, b.x);
        g_ccnt[tok0 + tid] = scnt[tid];
    }
}

// ============================================================
// K3: exact fp32 rescore of candidates -> g_kidx
// ============================================================
__global__ void __launch_bounds__(128) k_rescore(const float* __restrict__ E) {
    int tok = blockIdx.x * 4 + (threadIdx.x >> 5);
    int lid = threadIdx.x & 31;
    float z[16];
#pragma unroll
    for (int j = 0; j < 16; j++) z[j] = g_Zf[(size_t)tok * D_ + j * 32 + lid];

    int cnt = g_ccnt[tok];
    float amin = g_amin[tok];
    float best = FLT_MAX;
    int bi = 0x7fffffff;

    if (cnt <= CAP) {
        for (int c = 0; c < cnt; c++) {
            float2 cd = g_cand[tok][c];
            if (cd.x > amin + MARGIN_F) continue;      // warp-uniform
            int k = __float_as_int(cd.y);
            float p = 0.f;
            const float* er = E + (size_t)k * D_;
#pragma unroll
            for (int j = 0; j < 16; j++) p += z[j] * er[j * 32 + lid];
#pragma unroll
            for (int o = 16; o > 0; o >>= 1) p += __shfl_down_sync(0xffffffffu, p, o);
            if (lid == 0) {
                float dist = g_esq[k] - 2.0f * p;
                if (dist < best || (dist == best && k < bi)) { best = dist; bi = k; }
            }
        }
    } else {
        // overflow safety net: exact scan of all codes (rare)
        for (int k = 0; k < K_; k++) {
            float p = 0.f;
            const float* er = E + (size_t)k * D_;
#pragma unroll
            for (int j = 0; j < 16; j++) p += z[j] * er[j * 32 + lid];
#pragma unroll
            for (int o = 16; o > 0; o >>= 1) p += __shfl_down_sync(0xffffffffu, p, o);
            if (lid == 0) {
                float dist = g_esq[k] - 2.0f * p;
                if (dist < best) { best = dist; bi = k; }
            }
        }
    }
    if (lid == 0) g_kidx[tok] = bi;
}

// ============================================================
// K4: gather + NCHW output + loss partial
// ============================================================
__global__ void __launch_bounds__(256) k_output(const float* __restrict__ X,
                                                const float* __restrict__ E,
                                                float* __restrict__ out) {
    __shared__ float S[64][65];
    __shared__ int karr[64];
    __shared__ float rbuf[8];
    int t = threadIdx.x;
    int base = blockIdx.x * 64;
    int b = base >> 10, hw0 = base & 1023;
    if (t < 64) karr[t] = g_kidx[base + t];
    __syncthreads();

    float lsum = 0.f;
    size_t blk_base = (size_t)b * D_ * HW_ + hw0;
    for (int dc = 0; dc < D_; dc += 64) {
#pragma unroll
        for (int i = 0; i < 4; i++) {
            int m = (t >> 4) + i * 16;
            int dl = (t & 15) * 4;
            float4 q = *(const float4*)&E[(size_t)karr[m] * D_ + dc + dl];
            S[m][dl] = q.x; S[m][dl + 1] = q.y; S[m][dl + 2] = q.z; S[m][dl + 3] = q.w;
        }
        __syncthreads();
        int hwl = t & 63;
#pragma unroll
        for (int i = 0; i < 16; i++) {
            int dl = (t >> 6) + i * 4;
            size_t addr = blk_base + (size_t)(dc + dl) * HW_ + hwl;
            float z = X[addr];
            float q = S[hwl][dl];
            float df = z - q;
            lsum += df * df;
            out[addr] = q;
        }
        __syncthreads();
    }
#pragma unroll
    for (int o = 16; o > 0; o >>= 1) lsum += __shfl_down_sync(0xffffffffu, lsum, o);
    if ((t & 31) == 0) rbuf[t >> 5] = lsum;
    __syncthreads();
    if (t == 0) {
        float s = 0.f;
#pragma unroll
        for (int w = 0; w < 8; w++) s += rbuf[w];
        atomicAdd(&g_loss, (double)s);
    }
}

__global__ void k_finalize(float* __restrict__ out, int out_size) {
    if (out_size > N_ * D_)
        out[N_ * D_] = (float)(1.25 * g_loss / ((double)N_ * (double)D_));
}

// ============================================================
extern "C" void kernel_launch(void* const* d_in, const int* in_sizes, int n_in,
                              void* d_out, int out_size) {
    const float* X = (const float*)d_in[0];
    const float* E = (const float*)d_in[1];
    if (n_in >= 2 && in_sizes[0] == K_ * D_ && in_sizes[1] == N_ * D_) {
        const float* tmp = X; X = E; E = tmp;
    }
    float* out = (float*)d_out;

    static int smem_set = 0;
    if (!smem_set) {
        cudaFuncSetAttribute(k_gemm, cudaFuncAttributeMaxDynamicSharedMemorySize, SM_TOTAL);
        smem_set = 1;
    }

    k_prep_z<<<dim3(HW_ / 32, D_ / 32, B_), dim3(32, 8)>>>(X);
    k_prep_e<<<K_, 128>>>(E);
    k_gemm<<<N_ / TOK_PER_CTA, 256, SM_TOTAL>>>();
    k_rescore<<<N_ / 4, 128>>>(E);
    k_output<<<N_ / 64, 256>>>(X, E, out);
    k_finalize<<<1, 1>>>(out, out_size);
}